// round 3
// baseline (speedup 1.0000x reference)
#include <cuda_runtime.h>

#define BB 16
#define FF 257
#define MMDIM 6
#define TTDIM 1000
#define BF (BB*FF)
#define EPSV 1e-6f
#define EPS2V 1e-6f
#define NPAIR 21
#define TG 12
#define CHUNK 84

#define NQ (BF*36)            // 148032 Q entries (complex); harness keeps real part only
#define NXT (BF*6000)         // 24672000 xt entries

// ---------------- scratch (device globals; no runtime allocation) ----------------
__device__ float2 d_V[BF * 216];   // V[bf][k][m][n]
__device__ float2 d_C[BF * 36];    // C[bf][m][n] = sum_t x x^H (unnormalized)
__device__ float2 d_Q[BF * 36];    // working Q
__device__ float  d_part[BF];      // per-(b,f) partial trace(Q C Q^H)
__device__ float  d_sinv[BB];      // 1/scale
__device__ float  d_rs[BB];        // rsqrt(max(scale,1e-6))

static __device__ const int c_pm[NPAIR] = {0,0,0,0,0,0,1,1,1,1,1,2,2,2,2,3,3,3,4,4,5};
static __device__ const int c_pn[NPAIR] = {0,1,2,3,4,5,1,2,3,4,5,2,3,4,5,3,4,5,4,5,5};

// ---------------- K1: weighted covariances V, plain covariance C, Q copy ----------
__global__ __launch_bounds__(256, 2) void k_cov(
    const float* __restrict__ r,
    const float* __restrict__ Qre, const float* __restrict__ Qim,
    const float* __restrict__ xre, const float* __restrict__ xim)
{
    extern __shared__ float smem[];
    float*  sr  = smem;                                   // 6000 floats
    float2* sx  = reinterpret_cast<float2*>(smem + 6000); // 6000 float2
    float*  red = smem + 18000;                           // 252*14 floats

    const int bf  = blockIdx.x;
    const int tid = threadIdx.x;
    const size_t base = (size_t)bf * 6000;
    const float* rg = r   + base;
    const float* xr = xre + base;
    const float* xi = xim + base;

    for (int i = tid; i < 6000; i += 256) {
        sr[i] = rg[i];
        sx[i] = make_float2(xr[i], xi[i]);
    }
    __syncthreads();

    if (tid < NPAIR * TG) {
        const int pair = tid / TG, g = tid % TG;
        const int m = c_pm[pair], n = c_pn[pair];
        const float2* xm = sx + m * 1000;
        const float2* xn = sx + n * 1000;
        float aR[6] = {0,0,0,0,0,0}, aI[6] = {0,0,0,0,0,0};
        float cR = 0.f, cI = 0.f;
        const int t0 = g * CHUNK;
        const int t1 = (t0 + CHUNK < TTDIM) ? (t0 + CHUNK) : TTDIM;
        for (int t = t0; t < t1; ++t) {
            float2 a = xm[t], b = xn[t];
            float crR = a.x * b.x + a.y * b.y;   // x_m * conj(x_n)
            float crI = a.y * b.x - a.x * b.y;
            cR += crR; cI += crI;
            #pragma unroll
            for (int k = 0; k < 6; ++k) {
                float rv = sr[k * 1000 + t];
                aR[k] = fmaf(rv, crR, aR[k]);
                aI[k] = fmaf(rv, crI, aI[k]);
            }
        }
        float* rp = red + tid * 14;
        #pragma unroll
        for (int k = 0; k < 6; ++k) { rp[k] = aR[k]; rp[6 + k] = aI[k]; }
        rp[12] = cR; rp[13] = cI;
    }
    __syncthreads();

    if (tid < NPAIR) {
        float s[14];
        #pragma unroll
        for (int j = 0; j < 14; ++j) s[j] = 0.f;
        for (int g = 0; g < TG; ++g) {
            const float* rp = red + (tid * TG + g) * 14;
            #pragma unroll
            for (int j = 0; j < 14; ++j) s[j] += rp[j];
        }
        const int m = c_pm[tid], n = c_pn[tid];
        const float invT = 1.0f / (float)TTDIM;
        float2* Vg = d_V + (size_t)bf * 216;
        #pragma unroll
        for (int k = 0; k < 6; ++k) {
            float vr = s[k] * invT + ((m == n) ? EPSV : 0.f);
            float vi = s[6 + k] * invT;
            Vg[(k * 6 + m) * 6 + n] = make_float2(vr,  vi);
            Vg[(k * 6 + n) * 6 + m] = make_float2(vr, -vi);
        }
        float2* Cg = d_C + (size_t)bf * 36;
        Cg[m * 6 + n] = make_float2(s[12],  s[13]);
        Cg[n * 6 + m] = make_float2(s[12], -s[13]);
    }
    if (tid < 36) {
        const size_t qi = (size_t)bf * 36 + tid;
        d_Q[qi] = make_float2(Qre[qi], Qim[qi]);
    }
}

// ---------------- K2: one ISS iteration (6 sequential k-steps) + trace partial -----
__global__ __launch_bounds__(64) void k_iss(int apply_pre)
{
    __shared__ float2 sV[216], sC[36], sQ[36], sVq[36], sv[6], sq[6];
    const int bf = blockIdx.x, b = bf / FF;
    const int tid = threadIdx.x;

    for (int i = tid; i < 216; i += 64) sV[i] = d_V[(size_t)bf * 216 + i];
    const float rs = apply_pre ? d_rs[b] : 1.0f;
    if (tid < 36) {
        sC[tid] = d_C[(size_t)bf * 36 + tid];
        float2 q = d_Q[(size_t)bf * 36 + tid];
        sQ[tid] = make_float2(q.x * rs, q.y * rs);
    }
    __syncthreads();

    for (int k = 0; k < 6; ++k) {
        if (tid < 6) sq[tid] = sQ[k * 6 + tid];       // snapshot row k
        __syncthreads();
        if (tid < 36) {                                // Vq[kk][m] = sum_n V*conj(q)
            const int kk = tid / 6, m = tid % 6;
            float ar = 0.f, ai = 0.f;
            #pragma unroll
            for (int n = 0; n < 6; ++n) {
                float2 V = sV[(kk * 6 + m) * 6 + n];
                float2 q = sq[n];
                ar += V.x * q.x + V.y * q.y;
                ai += V.y * q.x - V.x * q.y;
            }
            sVq[tid] = make_float2(ar, ai);
        }
        __syncthreads();
        if (tid < 6) {
            const int kk = tid;
            float qvq = 0.f, nr = 0.f, ni = 0.f;
            #pragma unroll
            for (int m = 0; m < 6; ++m) {
                float2 q = sq[m], Vq = sVq[kk * 6 + m], Qe = sQ[kk * 6 + m];
                qvq += q.x * Vq.x - q.y * Vq.y;        // Re(q . Vq)
                nr  += Qe.x * Vq.x - Qe.y * Vq.y;      // Q . Vq (no conj)
                ni  += Qe.x * Vq.y + Qe.y * Vq.x;
            }
            qvq = fmaxf(qvq, EPS2V);
            const float inv = 1.0f / qvq;
            float2 vv = make_float2(nr * inv, ni * inv);
            if (kk == k) vv = make_float2(1.0f - rsqrtf(qvq), 0.f);
            sv[kk] = vv;
        }
        __syncthreads();
        if (tid < 36) {                                // Q -= v outer q
            const int kk = tid / 6, m = tid % 6;
            float2 vv = sv[kk], q = sq[m], Qe = sQ[tid];
            Qe.x -= vv.x * q.x - vv.y * q.y;
            Qe.y -= vv.x * q.y + vv.y * q.x;
            sQ[tid] = Qe;
        }
        __syncthreads();
    }

    // trace(Q C Q^H): QC = Q*C, then sum Re(QC .* conj(Q))
    if (tid < 36) {
        const int m = tid / 6, n = tid % 6;
        float ar = 0.f, ai = 0.f;
        #pragma unroll
        for (int p = 0; p < 6; ++p) {
            float2 a = sQ[m * 6 + p], c = sC[p * 6 + n];
            ar += a.x * c.x - a.y * c.y;
            ai += a.x * c.y + a.y * c.x;
        }
        sVq[tid] = make_float2(ar, ai);
    }
    __syncthreads();
    if (tid == 0) {
        float s = 0.f;
        for (int i = 0; i < 36; ++i) {
            float2 qc = sVq[i], q = sQ[i];
            s += qc.x * q.x + qc.y * q.y;              // Re(qc * conj(q))
        }
        d_part[bf] = s;
    }
    if (tid < 36) d_Q[(size_t)bf * 36 + tid] = sQ[tid];
}

// ---------------- K3: per-batch scale from trace partials (deterministic) ----------
__global__ __launch_bounds__(256) void k_scale()
{
    __shared__ float red[256];
    const int b = blockIdx.x, tid = threadIdx.x;
    float s = 0.f;
    for (int i = tid; i < FF; i += 256) s += d_part[b * FF + i];
    red[tid] = s;
    __syncthreads();
    for (int o = 128; o > 0; o >>= 1) {
        if (tid < o) red[tid] += red[tid + o];
        __syncthreads();
    }
    if (tid == 0) {
        const float scale = red[0] / (float)(FF * MMDIM * TTDIM);
        d_sinv[b] = 1.0f / scale;
        d_rs[b]   = rsqrtf(fmaxf(scale, 1e-6f));
    }
}

// ---------------- K4: final Q output + xt = |Q2 x|^2 / scale2 ----------------------
// Layout (deduced from out_size = NQ + NXT float32):
//   out[0 : NQ)        = real(Q_out)   (complex64 -> float32 drops imag)
//   out[NQ : NQ+NXT)   = xt
__global__ __launch_bounds__(256) void k_final(
    const float* __restrict__ xre, const float* __restrict__ xim,
    float* __restrict__ out)
{
    __shared__ float2 sQ[36];
    __shared__ float sI, sR;
    const int bf = blockIdx.x, b = bf / FF, tid = threadIdx.x;
    if (tid < 36) sQ[tid] = d_Q[(size_t)bf * 36 + tid];
    if (tid == 36) sI = d_sinv[b];
    if (tid == 37) sR = d_rs[b];
    __syncthreads();

    if (tid < 36) {
        out[(size_t)bf * 36 + tid] = sQ[tid].x * sR;   // real part only
    }

    float Qr[36], Qi[36];
    #pragma unroll
    for (int i = 0; i < 36; ++i) { Qr[i] = sQ[i].x; Qi[i] = sQ[i].y; }
    const float inv = sI;

    const size_t base = (size_t)bf * 6000;
    const float* xr = xre + base;
    const float* xi = xim + base;
    float* xt = out + (size_t)NQ + base;

    for (int t = tid; t < TTDIM; t += 256) {
        float vr[6], vi[6];
        #pragma unroll
        for (int n = 0; n < 6; ++n) { vr[n] = xr[n * 1000 + t]; vi[n] = xi[n * 1000 + t]; }
        #pragma unroll
        for (int m = 0; m < 6; ++m) {
            float ar = 0.f, ai = 0.f;
            #pragma unroll
            for (int n = 0; n < 6; ++n) {
                const float qr = Qr[m * 6 + n], qi2 = Qi[m * 6 + n];
                ar += qr * vr[n] - qi2 * vi[n];
                ai += qr * vi[n] + qi2 * vr[n];
            }
            xt[m * 1000 + t] = (ar * ar + ai * ai) * inv;
        }
    }
}

// ---------------- launch ----------------
extern "C" void kernel_launch(void* const* d_in, const int* in_sizes, int n_in,
                              void* d_out, int out_size)
{
    const float* r   = (const float*)d_in[0];
    const float* Qre = (const float*)d_in[1];
    const float* Qim = (const float*)d_in[2];
    const float* xre = (const float*)d_in[3];
    const float* xim = (const float*)d_in[4];
    float* out = (float*)d_out;

    const int smem_cov = (18000 + NPAIR * TG * 14) * (int)sizeof(float); // 86112 B
    cudaFuncSetAttribute(k_cov, cudaFuncAttributeMaxDynamicSharedMemorySize, smem_cov);

    k_cov<<<BF, 256, smem_cov>>>(r, Qre, Qim, xre, xim);
    k_iss<<<BF, 64>>>(0);
    k_scale<<<BB, 256>>>();
    k_iss<<<BF, 64>>>(1);
    k_scale<<<BB, 256>>>();
    k_final<<<BF, 256>>>(xre, xim, out);
}

// round 5
// speedup vs baseline: 1.1038x; 1.1038x over previous
#include <cuda_runtime.h>

#define BB 16
#define FF 257
#define MMDIM 6
#define TTDIM 1000
#define BF (BB*FF)
#define EPSV 1e-6f
#define EPS2V 1e-6f
#define NPAIR 21
#define TG 12

#define NQ (BF*36)            // Q entries (complex); harness keeps real part only
#define NXT (BF*6000)         // xt entries

// packed f32x2 helpers (sm_100+)
#define FMA_F32X2(d, a, b, c) \
    asm("fma.rn.f32x2 %0, %1, %2, %3;" : "=l"(d) : "l"(a), "l"(b), "l"(c))
#define ADD_F32X2(d, a, b) \
    asm("add.rn.f32x2 %0, %1, %2;" : "=l"(d) : "l"(a), "l"(b))
#define PACK_F32X2(d, lo, hi) \
    asm("mov.b64 %0, {%1, %2};" : "=l"(d) : "f"(lo), "f"(hi))
#define UNPACK_F32X2(lo, hi, s) \
    asm("mov.b64 {%0, %1}, %2;" : "=f"(lo), "=f"(hi) : "l"(s))

// ---------------- scratch (device globals; no runtime allocation) ----------------
__device__ float2 d_V[BF * 216];   // V[bf][k][m][n]
__device__ float2 d_C[BF * 36];    // C[bf][m][n] = sum_t x x^H (unnormalized)
__device__ float2 d_Q[BF * 36];    // working Q
__device__ float  d_part[BF];      // per-(b,f) partial trace(Q C Q^H)
__device__ float  d_sinv[BB];      // 1/scale
__device__ float  d_rs[BB];        // rsqrt(max(scale,1e-6))

static __device__ const int c_pm[NPAIR] = {0,0,0,0,0,0,1,1,1,1,1,2,2,2,2,3,3,3,4,4,5};
static __device__ const int c_pn[NPAIR] = {0,1,2,3,4,5,1,2,3,4,5,2,3,4,5,3,4,5,4,5,5};

// ---------------- K1: weighted covariances V, plain covariance C, Q copy ----------
// smem: srd (r duplicated as (rv,rv), 48KB) + sx (x as float2, 48KB); the
// 14KB reduction buffer is ALIASED over srd after a barrier.
__global__ __launch_bounds__(256, 2) void k_cov(
    const float* __restrict__ r,
    const float* __restrict__ Qre, const float* __restrict__ Qim,
    const float* __restrict__ xre, const float* __restrict__ xim)
{
    extern __shared__ float smem[];
    float2* srd = reinterpret_cast<float2*>(smem);          // 6000 float2
    float2* sx  = reinterpret_cast<float2*>(smem) + 6000;   // 6000 float2
    float*  red = smem;                                     // aliased later

    const int bf  = blockIdx.x;
    const int tid = threadIdx.x;
    const size_t base = (size_t)bf * 6000;

    // Q copy (independent of smem)
    if (tid < 36) {
        const size_t qi = (size_t)bf * 36 + tid;
        d_Q[qi] = make_float2(Qre[qi], Qim[qi]);
    }

    // vectorized tile load: 1500 float4 per tensor
    {
        const float4* rg4 = reinterpret_cast<const float4*>(r   + base);
        const float4* xr4 = reinterpret_cast<const float4*>(xre + base);
        const float4* xi4 = reinterpret_cast<const float4*>(xim + base);
        for (int i = tid; i < 1500; i += 256) {
            float4 rv = rg4[i], xr_ = xr4[i], xi_ = xi4[i];
            const int j = i * 4;
            srd[j]   = make_float2(rv.x, rv.x);
            srd[j+1] = make_float2(rv.y, rv.y);
            srd[j+2] = make_float2(rv.z, rv.z);
            srd[j+3] = make_float2(rv.w, rv.w);
            sx[j]    = make_float2(xr_.x, xi_.x);
            sx[j+1]  = make_float2(xr_.y, xi_.y);
            sx[j+2]  = make_float2(xr_.z, xi_.z);
            sx[j+3]  = make_float2(xr_.w, xi_.w);
        }
    }
    __syncthreads();

    unsigned long long acc[6] = {0,0,0,0,0,0};  // packed (aR, aI) per k
    unsigned long long accC  = 0;               // packed (cR, cI)

    if (tid < NPAIR * TG) {
        const int pair = tid / TG, g = tid % TG;
        const int m = c_pm[pair], n = c_pn[pair];
        const float2* xm = sx + m * 1000;
        const float2* xn = sx + n * 1000;
        const unsigned long long* rr =
            reinterpret_cast<const unsigned long long*>(srd);

        // interleaved t: adjacent lanes -> adjacent t -> conflict-free LDS
        for (int t = g; t < TTDIM; t += TG) {
            float2 a = xm[t], b = xn[t];
            float crR = fmaf(a.x, b.x,  a.y * b.y);   // Re(x_m conj(x_n))
            float crI = fmaf(a.y, b.x, -a.x * b.y);   // Im
            unsigned long long cr;
            PACK_F32X2(cr, crR, crI);
            ADD_F32X2(accC, accC, cr);
            #pragma unroll
            for (int k = 0; k < 6; ++k) {
                unsigned long long rv2 = rr[k * 1000 + t];  // (rv, rv)
                FMA_F32X2(acc[k], rv2, cr, acc[k]);
            }
        }
    }
    __syncthreads();   // everyone done reading srd/sx -> safe to alias red

    if (tid < NPAIR * TG) {
        float* rp = red + tid * 14;
        #pragma unroll
        for (int k = 0; k < 6; ++k) {
            float aR, aI;
            UNPACK_F32X2(aR, aI, acc[k]);
            rp[k] = aR; rp[6 + k] = aI;
        }
        float cR, cI;
        UNPACK_F32X2(cR, cI, accC);
        rp[12] = cR; rp[13] = cI;
    }
    __syncthreads();

    if (tid < NPAIR) {
        float s[14];
        #pragma unroll
        for (int j = 0; j < 14; ++j) s[j] = 0.f;
        for (int g = 0; g < TG; ++g) {
            const float* rp = red + (tid * TG + g) * 14;
            #pragma unroll
            for (int j = 0; j < 14; ++j) s[j] += rp[j];
        }
        const int m = c_pm[tid], n = c_pn[tid];
        const float invT = 1.0f / (float)TTDIM;
        float2* Vg = d_V + (size_t)bf * 216;
        #pragma unroll
        for (int k = 0; k < 6; ++k) {
            float vr = s[k] * invT + ((m == n) ? EPSV : 0.f);
            float vi = s[6 + k] * invT;
            Vg[(k * 6 + m) * 6 + n] = make_float2(vr,  vi);
            Vg[(k * 6 + n) * 6 + m] = make_float2(vr, -vi);
        }
        float2* Cg = d_C + (size_t)bf * 36;
        Cg[m * 6 + n] = make_float2(s[12],  s[13]);
        Cg[n * 6 + m] = make_float2(s[12], -s[13]);
    }
}

// ---------------- K2: one ISS iteration (6 sequential k-steps) + trace partial -----
// (snapshot phase has its own barrier: folding it into the update phase is a
//  cross-warp race — tids 0..35 span two warps)
__global__ __launch_bounds__(64) void k_iss(int apply_pre)
{
    __shared__ float2 sV[216], sC[36], sQ[36], sVq[36], sv[6], sq[6];
    const int bf = blockIdx.x, b = bf / FF;
    const int tid = threadIdx.x;

    for (int i = tid; i < 216; i += 64) sV[i] = d_V[(size_t)bf * 216 + i];
    const float rs = apply_pre ? d_rs[b] : 1.0f;
    if (tid < 36) {
        sC[tid] = d_C[(size_t)bf * 36 + tid];
        float2 q = d_Q[(size_t)bf * 36 + tid];
        sQ[tid] = make_float2(q.x * rs, q.y * rs);
    }
    __syncthreads();

    for (int k = 0; k < 6; ++k) {
        if (tid < 6) sq[tid] = sQ[k * 6 + tid];       // snapshot row k
        __syncthreads();
        if (tid < 36) {                                // Vq[kk][m] = sum_n V*conj(q)
            const int kk = tid / 6, m = tid % 6;
            float ar = 0.f, ai = 0.f;
            #pragma unroll
            for (int n = 0; n < 6; ++n) {
                float2 V = sV[(kk * 6 + m) * 6 + n];
                float2 q = sq[n];
                ar += V.x * q.x + V.y * q.y;
                ai += V.y * q.x - V.x * q.y;
            }
            sVq[tid] = make_float2(ar, ai);
        }
        __syncthreads();
        if (tid < 6) {
            const int kk = tid;
            float qvq = 0.f, nr = 0.f, ni = 0.f;
            #pragma unroll
            for (int m = 0; m < 6; ++m) {
                float2 q = sq[m], Vq = sVq[kk * 6 + m], Qe = sQ[kk * 6 + m];
                qvq += q.x * Vq.x - q.y * Vq.y;        // Re(q . Vq)
                nr  += Qe.x * Vq.x - Qe.y * Vq.y;      // Q . Vq (no conj)
                ni  += Qe.x * Vq.y + Qe.y * Vq.x;
            }
            qvq = fmaxf(qvq, EPS2V);
            const float inv = 1.0f / qvq;
            float2 vv = make_float2(nr * inv, ni * inv);
            if (kk == k) vv = make_float2(1.0f - rsqrtf(qvq), 0.f);
            sv[kk] = vv;
        }
        __syncthreads();
        if (tid < 36) {                                // Q -= v outer q
            const int kk = tid / 6, m = tid % 6;
            float2 vv = sv[kk], q = sq[m], Qe = sQ[tid];
            Qe.x -= vv.x * q.x - vv.y * q.y;
            Qe.y -= vv.x * q.y + vv.y * q.x;
            sQ[tid] = Qe;
        }
        __syncthreads();
    }

    // trace(Q C Q^H): QC = Q*C, then sum Re(QC .* conj(Q))
    if (tid < 36) {
        const int m = tid / 6, n = tid % 6;
        float ar = 0.f, ai = 0.f;
        #pragma unroll
        for (int p = 0; p < 6; ++p) {
            float2 a = sQ[m * 6 + p], c = sC[p * 6 + n];
            ar += a.x * c.x - a.y * c.y;
            ai += a.x * c.y + a.y * c.x;
        }
        sVq[tid] = make_float2(ar, ai);
    }
    __syncthreads();
    if (tid == 0) {
        float s = 0.f;
        for (int i = 0; i < 36; ++i) {
            float2 qc = sVq[i], q = sQ[i];
            s += qc.x * q.x + qc.y * q.y;              // Re(qc * conj(q))
        }
        d_part[bf] = s;
    }
    if (tid < 36) d_Q[(size_t)bf * 36 + tid] = sQ[tid];
}

// ---------------- K3: per-batch scale from trace partials (deterministic) ----------
__global__ __launch_bounds__(256) void k_scale()
{
    __shared__ float red[256];
    const int b = blockIdx.x, tid = threadIdx.x;
    float s = 0.f;
    for (int i = tid; i < FF; i += 256) s += d_part[b * FF + i];
    red[tid] = s;
    __syncthreads();
    for (int o = 128; o > 0; o >>= 1) {
        if (tid < o) red[tid] += red[tid + o];
        __syncthreads();
    }
    if (tid == 0) {
        const float scale = red[0] / (float)(FF * MMDIM * TTDIM);
        d_sinv[b] = 1.0f / scale;
        d_rs[b]   = rsqrtf(fmaxf(scale, 1e-6f));
    }
}

// ---------------- K4: final Q output + xt = |Q2 x|^2 / scale2 ----------------------
// out[0:NQ) = real(Q_out); out[NQ:NQ+NXT) = xt. float4 I/O, Q in smem.
__global__ __launch_bounds__(256) void k_final(
    const float* __restrict__ xre, const float* __restrict__ xim,
    float* __restrict__ out)
{
    __shared__ float sQr[36], sQi[36];
    __shared__ float sI;
    const int bf = blockIdx.x, b = bf / FF, tid = threadIdx.x;
    if (tid < 36) {
        float2 q = d_Q[(size_t)bf * 36 + tid];
        sQr[tid] = q.x;
        sQi[tid] = q.y;
        out[(size_t)bf * 36 + tid] = q.x * d_rs[b];    // real part of Q_out
    }
    if (tid == 64) sI = d_sinv[b];
    __syncthreads();

    if (tid < 250) {
        const size_t base = (size_t)bf * 6000;
        const float4* xr4 = reinterpret_cast<const float4*>(xre + base);
        const float4* xi4 = reinterpret_cast<const float4*>(xim + base);
        float4* xt4 = reinterpret_cast<float4*>(out + (size_t)NQ + base);
        const float inv = sI;

        float4 vr[6], vi[6];
        #pragma unroll
        for (int n = 0; n < 6; ++n) {
            vr[n] = xr4[n * 250 + tid];
            vi[n] = xi4[n * 250 + tid];
        }
        #pragma unroll
        for (int m = 0; m < 6; ++m) {
            float4 ar = make_float4(0,0,0,0), ai = make_float4(0,0,0,0);
            #pragma unroll
            for (int n = 0; n < 6; ++n) {
                const float qr = sQr[m * 6 + n], qi = sQi[m * 6 + n];
                ar.x = fmaf(qr, vr[n].x, fmaf(-qi, vi[n].x, ar.x));
                ar.y = fmaf(qr, vr[n].y, fmaf(-qi, vi[n].y, ar.y));
                ar.z = fmaf(qr, vr[n].z, fmaf(-qi, vi[n].z, ar.z));
                ar.w = fmaf(qr, vr[n].w, fmaf(-qi, vi[n].w, ar.w));
                ai.x = fmaf(qr, vi[n].x, fmaf(qi, vr[n].x, ai.x));
                ai.y = fmaf(qr, vi[n].y, fmaf(qi, vr[n].y, ai.y));
                ai.z = fmaf(qr, vi[n].z, fmaf(qi, vr[n].z, ai.z));
                ai.w = fmaf(qr, vi[n].w, fmaf(qi, vr[n].w, ai.w));
            }
            float4 o4;
            o4.x = (ar.x * ar.x + ai.x * ai.x) * inv;
            o4.y = (ar.y * ar.y + ai.y * ai.y) * inv;
            o4.z = (ar.z * ar.z + ai.z * ai.z) * inv;
            o4.w = (ar.w * ar.w + ai.w * ai.w) * inv;
            xt4[m * 250 + tid] = o4;
        }
    }
}

// ---------------- launch ----------------
extern "C" void kernel_launch(void* const* d_in, const int* in_sizes, int n_in,
                              void* d_out, int out_size)
{
    const float* r   = (const float*)d_in[0];
    const float* Qre = (const float*)d_in[1];
    const float* Qim = (const float*)d_in[2];
    const float* xre = (const float*)d_in[3];
    const float* xim = (const float*)d_in[4];
    float* out = (float*)d_out;

    const int smem_cov = 96000;   // 2 x 6000 float2
    cudaFuncSetAttribute(k_cov, cudaFuncAttributeMaxDynamicSharedMemorySize, smem_cov);

    k_cov<<<BF, 256, smem_cov>>>(r, Qre, Qim, xre, xim);
    k_iss<<<BF, 64>>>(0);
    k_scale<<<BB, 256>>>();
    k_iss<<<BF, 64>>>(1);
    k_scale<<<BB, 256>>>();
    k_final<<<BF, 256>>>(xre, xim, out);
}

// round 10
// speedup vs baseline: 1.5857x; 1.4367x over previous
#include <cuda_runtime.h>

#define BB 16
#define FF 257
#define MMDIM 6
#define TTDIM 1000
#define BF (BB*FF)
#define EPSV 1e-6f
#define EPS2V 1e-6f
#define NPAIR 21

#define NQ (BF*36)
#define NXT (BF*6000)

// packed f32x2 helpers (sm_100+)
#define FMA_F32X2(d, a, b, c) \
    asm("fma.rn.f32x2 %0, %1, %2, %3;" : "=l"(d) : "l"(a), "l"(b), "l"(c))
#define MUL_F32X2(d, a, b) \
    asm("mul.rn.f32x2 %0, %1, %2;" : "=l"(d) : "l"(a), "l"(b))
#define ADD_F32X2(d, a, b) \
    asm("add.rn.f32x2 %0, %1, %2;" : "=l"(d) : "l"(a), "l"(b))
#define UNPACK_F32X2(lo, hi, s) \
    asm("mov.b64 {%0, %1}, %2;" : "=f"(lo), "=f"(hi) : "l"(s))

__device__ __forceinline__ unsigned long long pk(float lo, float hi) {
    unsigned long long u;
    asm("mov.b64 %0, {%1, %2};" : "=l"(u) : "f"(lo), "f"(hi));
    return u;
}

// pair index -> (m, n), n >= m, row-major upper triangle
__host__ __device__ constexpr int PM(int p) {
    return p < 6 ? 0 : p < 11 ? 1 : p < 15 ? 2 : p < 18 ? 3 : p < 20 ? 4 : 5;
}
__host__ __device__ constexpr int PN(int p) {
    return p < 6 ? p : p < 11 ? p - 5 : p < 15 ? p - 9 : p < 18 ? p - 12
         : p < 20 ? p - 14 : 5;
}

// ---------------- scratch (device globals; no runtime allocation) ----------------
__device__ float2 d_V[BF * 216];   // V[bf][k][m][n]
__device__ float2 d_C[BF * 36];    // C[bf][m][n] = sum_t x x^H (unnormalized)
__device__ float2 d_Q[BF * 36];    // working Q
__device__ float  d_part[BF];      // per-(b,f) partial trace(Q C Q^H)
__device__ float  d_sinv[BB];      // 1/scale
__device__ float  d_rs[BB];        // rsqrt(max(scale,1e-6))

// ---------------- K1 main loop: one warp handles NP pairs, all t ------------------
// Accumulates in registers; a CONVERGED __syncthreads() (each of the 128
// threads calls cov_warp exactly once) separates the last tile read from the
// partial store into red, which ALIASES the tile.
template<int P0, int NP>
__device__ __forceinline__ void cov_warp(const float* __restrict__ sr,
                                         const float2* __restrict__ sx,
                                         int wid, int lane, float* red)
{
    unsigned long long acc[NP][6];
    unsigned long long accC[NP];
    #pragma unroll
    for (int j = 0; j < NP; ++j) {
        accC[j] = 0;
        #pragma unroll
        for (int k = 0; k < 6; ++k) acc[j][k] = 0;
    }

    for (int t = lane; t < TTDIM; t += 32) {
        float2 xv[6];
        #pragma unroll
        for (int m = 0; m < 6; ++m) xv[m] = sx[m * 1000 + t];
        unsigned long long rv2[6];
        #pragma unroll
        for (int k = 0; k < 6; ++k) {
            float rk = sr[k * 1000 + t];
            rv2[k] = pk(rk, rk);
        }
        #pragma unroll
        for (int j = 0; j < NP; ++j) {
            const int m = PM(P0 + j), n = PN(P0 + j);
            // cr = (crR, crI): crR = ax*bx + ay*by ; crI = ay*bx - ax*by
            unsigned long long axy = pk(xv[m].x,  xv[m].y);
            unsigned long long ayx = pk(xv[m].y, -xv[m].x);
            unsigned long long bxx = pk(xv[n].x,  xv[n].x);
            unsigned long long byy = pk(xv[n].y,  xv[n].y);
            unsigned long long cr;
            MUL_F32X2(cr, ayx, byy);
            FMA_F32X2(cr, axy, bxx, cr);
            ADD_F32X2(accC[j], accC[j], cr);
            #pragma unroll
            for (int k = 0; k < 6; ++k)
                FMA_F32X2(acc[j][k], rv2[k], cr, acc[j][k]);
        }
    }

    __syncthreads();   // tile dead block-wide; red alias now safe

    // partials: red[(wid*32+lane)*97 + j*16 + {0..5 aR, 6..11 aI, 12 cR, 13 cI}]
    float* rp = red + (size_t)(wid * 32 + lane) * 97;
    #pragma unroll
    for (int j = 0; j < NP; ++j) {
        #pragma unroll
        for (int k = 0; k < 6; ++k) {
            float aR, aI;
            UNPACK_F32X2(aR, aI, acc[j][k]);
            rp[j * 16 + k]     = aR;
            rp[j * 16 + 6 + k] = aI;
        }
        float cR, cI;
        UNPACK_F32X2(cR, cI, accC[j]);
        rp[j * 16 + 12] = cR;
        rp[j * 16 + 13] = cI;
    }
}

// ---------------- K1: weighted covariances V, plain covariance C, Q copy ----------
// smem: sr (6000 f, 24KB) + sx (6000 float2, 48KB); red (12416 f) + sred (294 f)
// aliased over the dead tile after the main loop.
__global__ __launch_bounds__(128, 2) void k_cov(
    const float* __restrict__ r,
    const float* __restrict__ Qre, const float* __restrict__ Qim,
    const float* __restrict__ xre, const float* __restrict__ xim)
{
    extern __shared__ float smem[];
    float*  sr   = smem;                                    // 6000 floats
    float2* sx   = reinterpret_cast<float2*>(smem + 6000);  // 6000 float2
    float*  red  = smem;                                    // aliased after barrier
    float*  sred = smem + 12416;                            // aliased after barrier

    const int bf  = blockIdx.x;
    const int tid = threadIdx.x;
    const int wid = tid >> 5, lane = tid & 31;
    const size_t base = (size_t)bf * 6000;

    if (tid < 36) {
        const size_t qi = (size_t)bf * 36 + tid;
        d_Q[qi] = make_float2(Qre[qi], Qim[qi]);
    }

    {   // vectorized tile load
        const float4* rg4 = reinterpret_cast<const float4*>(r   + base);
        const float4* xr4 = reinterpret_cast<const float4*>(xre + base);
        const float4* xi4 = reinterpret_cast<const float4*>(xim + base);
        float4* sr4 = reinterpret_cast<float4*>(sr);
        for (int i = tid; i < 1500; i += 128) {
            sr4[i] = rg4[i];
            float4 a = xr4[i], b = xi4[i];
            const int j = i * 4;
            sx[j]   = make_float2(a.x, b.x);
            sx[j+1] = make_float2(a.y, b.y);
            sx[j+2] = make_float2(a.z, b.z);
            sx[j+3] = make_float2(a.w, b.w);
        }
    }
    __syncthreads();

    if      (wid == 0) cov_warp<0, 6>(sr, sx, 0, lane, red);
    else if (wid == 1) cov_warp<6, 5>(sr, sx, 1, lane, red);
    else if (wid == 2) cov_warp<11,5>(sr, sx, 2, lane, red);
    else               cov_warp<16,5>(sr, sx, 3, lane, red);
    __syncthreads();   // partials stored -> reduce

    // reduce: 294 output scalars = 21 pairs x 14 components
    for (int s = tid; s < 294; s += 128) {
        const int pair = s / 14, comp = s % 14;
        const int w  = pair < 6 ? 0 : pair < 11 ? 1 : pair < 16 ? 2 : 3;
        const int j  = pair - (w == 0 ? 0 : w == 1 ? 6 : w == 2 ? 11 : 16);
        float acc = 0.f;
        const float* rp = red + (size_t)(w * 32) * 97 + j * 16 + comp;
        #pragma unroll 8
        for (int l = 0; l < 32; ++l) acc += rp[l * 97];
        sred[s] = acc;
    }
    __syncthreads();

    if (tid < NPAIR) {
        const float* s = sred + tid * 14;
        const int m = PM(tid), n = PN(tid);
        const float invT = 1.0f / (float)TTDIM;
        float2* Vg = d_V + (size_t)bf * 216;
        #pragma unroll
        for (int k = 0; k < 6; ++k) {
            float vr = s[k] * invT + ((m == n) ? EPSV : 0.f);
            float vi = s[6 + k] * invT;
            Vg[(k * 6 + m) * 6 + n] = make_float2(vr,  vi);
            Vg[(k * 6 + n) * 6 + m] = make_float2(vr, -vi);
        }
        float2* Cg = d_C + (size_t)bf * 36;
        Cg[m * 6 + n] = make_float2(s[12],  s[13]);
        Cg[n * 6 + m] = make_float2(s[12], -s[13]);
    }
}

// ---------------- K2: one ISS iteration, single warp per (b,f) --------------------
__global__ __launch_bounds__(32) void k_iss(int apply_pre)
{
    __shared__ float2 sV[216], sC[36], sQ[36], sVq[36], sv[6], sq[6];
    const int bf = blockIdx.x, b = bf / FF;
    const int lane = threadIdx.x;

    for (int i = lane; i < 216; i += 32) sV[i] = d_V[(size_t)bf * 216 + i];
    const float rs = apply_pre ? d_rs[b] : 1.0f;
    for (int i = lane; i < 36; i += 32) {
        sC[i] = d_C[(size_t)bf * 36 + i];
        float2 q = d_Q[(size_t)bf * 36 + i];
        sQ[i] = make_float2(q.x * rs, q.y * rs);
    }
    __syncwarp();

    for (int k = 0; k < 6; ++k) {
        if (lane < 6) sq[lane] = sQ[k * 6 + lane];       // snapshot row k
        __syncwarp();
        for (int it = lane; it < 36; it += 32) {          // Vq = V * conj(q)
            const int kk = it / 6, m = it % 6;
            float ar = 0.f, ai = 0.f;
            #pragma unroll
            for (int n = 0; n < 6; ++n) {
                float2 V = sV[(kk * 6 + m) * 6 + n];
                float2 q = sq[n];
                ar += V.x * q.x + V.y * q.y;
                ai += V.y * q.x - V.x * q.y;
            }
            sVq[it] = make_float2(ar, ai);
        }
        __syncwarp();
        if (lane < 6) {
            const int kk = lane;
            float qvq = 0.f, nr = 0.f, ni = 0.f;
            #pragma unroll
            for (int m = 0; m < 6; ++m) {
                float2 q = sq[m], Vq = sVq[kk * 6 + m], Qe = sQ[kk * 6 + m];
                qvq += q.x * Vq.x - q.y * Vq.y;
                nr  += Qe.x * Vq.x - Qe.y * Vq.y;
                ni  += Qe.x * Vq.y + Qe.y * Vq.x;
            }
            qvq = fmaxf(qvq, EPS2V);
            const float inv = 1.0f / qvq;
            float2 vv = make_float2(nr * inv, ni * inv);
            if (kk == k) vv = make_float2(1.0f - rsqrtf(qvq), 0.f);
            sv[kk] = vv;
        }
        __syncwarp();
        for (int it = lane; it < 36; it += 32) {          // Q -= v outer q
            const int kk = it / 6, m = it % 6;
            float2 vv = sv[kk], q = sq[m], Qe = sQ[it];
            Qe.x -= vv.x * q.x - vv.y * q.y;
            Qe.y -= vv.x * q.y + vv.y * q.x;
            sQ[it] = Qe;
        }
        __syncwarp();
    }

    // trace(Q C Q^H)
    for (int it = lane; it < 36; it += 32) {
        const int m = it / 6, n = it % 6;
        float ar = 0.f, ai = 0.f;
        #pragma unroll
        for (int p = 0; p < 6; ++p) {
            float2 a = sQ[m * 6 + p], c = sC[p * 6 + n];
            ar += a.x * c.x - a.y * c.y;
            ai += a.x * c.y + a.y * c.x;
        }
        sVq[it] = make_float2(ar, ai);
    }
    __syncwarp();
    float s = 0.f;
    for (int it = lane; it < 36; it += 32) {
        float2 qc = sVq[it], q = sQ[it];
        s += qc.x * q.x + qc.y * q.y;
    }
    #pragma unroll
    for (int o = 16; o; o >>= 1) s += __shfl_down_sync(0xffffffffu, s, o);
    if (lane == 0) d_part[bf] = s;
    for (int i = lane; i < 36; i += 32) d_Q[(size_t)bf * 36 + i] = sQ[i];
}

// ---------------- K3: per-batch scale from trace partials -------------------------
__global__ __launch_bounds__(256) void k_scale()
{
    __shared__ float red[256];
    const int b = blockIdx.x, tid = threadIdx.x;
    float s = 0.f;
    for (int i = tid; i < FF; i += 256) s += d_part[b * FF + i];
    red[tid] = s;
    __syncthreads();
    for (int o = 128; o > 0; o >>= 1) {
        if (tid < o) red[tid] += red[tid + o];
        __syncthreads();
    }
    if (tid == 0) {
        const float scale = red[0] / (float)(FF * MMDIM * TTDIM);
        d_sinv[b] = 1.0f / scale;
        d_rs[b]   = rsqrtf(fmaxf(scale, 1e-6f));
    }
}

// ---------------- K4: final Q output + xt = |Q2 x|^2 / scale2 ---------------------
__global__ __launch_bounds__(256) void k_final(
    const float* __restrict__ xre, const float* __restrict__ xim,
    float* __restrict__ out)
{
    __shared__ float sQr[36], sQi[36];
    __shared__ float sI;
    const int bf = blockIdx.x, b = bf / FF, tid = threadIdx.x;
    if (tid < 36) {
        float2 q = d_Q[(size_t)bf * 36 + tid];
        sQr[tid] = q.x;
        sQi[tid] = q.y;
        out[(size_t)bf * 36 + tid] = q.x * d_rs[b];
    }
    if (tid == 64) sI = d_sinv[b];
    __syncthreads();

    if (tid < 250) {
        const size_t base = (size_t)bf * 6000;
        const float4* xr4 = reinterpret_cast<const float4*>(xre + base);
        const float4* xi4 = reinterpret_cast<const float4*>(xim + base);
        float4* xt4 = reinterpret_cast<float4*>(out + (size_t)NQ + base);
        const float inv = sI;

        float4 vr[6], vi[6];
        #pragma unroll
        for (int n = 0; n < 6; ++n) {
            vr[n] = xr4[n * 250 + tid];
            vi[n] = xi4[n * 250 + tid];
        }
        #pragma unroll
        for (int m = 0; m < 6; ++m) {
            float4 ar = make_float4(0,0,0,0), ai = make_float4(0,0,0,0);
            #pragma unroll
            for (int n = 0; n < 6; ++n) {
                const float qr = sQr[m * 6 + n], qi = sQi[m * 6 + n];
                ar.x = fmaf(qr, vr[n].x, fmaf(-qi, vi[n].x, ar.x));
                ar.y = fmaf(qr, vr[n].y, fmaf(-qi, vi[n].y, ar.y));
                ar.z = fmaf(qr, vr[n].z, fmaf(-qi, vi[n].z, ar.z));
                ar.w = fmaf(qr, vr[n].w, fmaf(-qi, vi[n].w, ar.w));
                ai.x = fmaf(qr, vi[n].x, fmaf(qi, vr[n].x, ai.x));
                ai.y = fmaf(qr, vi[n].y, fmaf(qi, vr[n].y, ai.y));
                ai.z = fmaf(qr, vi[n].z, fmaf(qi, vr[n].z, ai.z));
                ai.w = fmaf(qr, vi[n].w, fmaf(qi, vr[n].w, ai.w));
            }
            float4 o4;
            o4.x = (ar.x * ar.x + ai.x * ai.x) * inv;
            o4.y = (ar.y * ar.y + ai.y * ai.y) * inv;
            o4.z = (ar.z * ar.z + ai.z * ai.z) * inv;
            o4.w = (ar.w * ar.w + ai.w * ai.w) * inv;
            xt4[m * 250 + tid] = o4;
        }
    }
}

// ---------------- launch ----------------
extern "C" void kernel_launch(void* const* d_in, const int* in_sizes, int n_in,
                              void* d_out, int out_size)
{
    const float* r   = (const float*)d_in[0];
    const float* Qre = (const float*)d_in[1];
    const float* Qim = (const float*)d_in[2];
    const float* xre = (const float*)d_in[3];
    const float* xim = (const float*)d_in[4];
    float* out = (float*)d_out;

    const int smem_cov = 18000 * (int)sizeof(float);   // 72000 B
    cudaFuncSetAttribute(k_cov, cudaFuncAttributeMaxDynamicSharedMemorySize, smem_cov);

    k_cov<<<BF, 128, smem_cov>>>(r, Qre, Qim, xre, xim);
    k_iss<<<BF, 32>>>(0);
    k_scale<<<BB, 256>>>();
    k_iss<<<BF, 32>>>(1);
    k_scale<<<BB, 256>>>();
    k_final<<<BF, 256>>>(xre, xim, out);
}

// round 13
// speedup vs baseline: 1.8260x; 1.1515x over previous
#include <cuda_runtime.h>
#include <cstdint>

#define BB 16
#define FF 257
#define TTDIM 1000
#define BF (BB*FF)
#define EPSV 1e-6f
#define EPS2V 1e-6f
#define NPAIR 21

#define NQ (BF*36)
#define NXT (BF*6000)

// chunked smem layout for k_cov: 4 chunks x (3 regions x 6 m x 256 floats)
#define CH_STRIDE 4608      // floats per chunk (3*1536)
#define RG_STRIDE 1536      // floats per region (6*256)
#define M_STRIDE  256
#define SMEM_FLOATS (4*CH_STRIDE)   // 18432 floats = 73728 B

typedef unsigned long long ULL;

// packed f32x2 helpers (sm_100+)
#define FMA_F32X2(d, a, b, c) \
    asm("fma.rn.f32x2 %0, %1, %2, %3;" : "=l"(d) : "l"(a), "l"(b), "l"(c))
#define MUL_F32X2(d, a, b) \
    asm("mul.rn.f32x2 %0, %1, %2;" : "=l"(d) : "l"(a), "l"(b))
#define ADD_F32X2(d, a, b) \
    asm("add.rn.f32x2 %0, %1, %2;" : "=l"(d) : "l"(a), "l"(b))
#define UNPACK_F32X2(lo, hi, s) \
    asm("mov.b64 {%0, %1}, %2;" : "=f"(lo), "=f"(hi) : "l"(s))

__device__ __forceinline__ ULL pk(float lo, float hi) {
    ULL u;
    asm("mov.b64 %0, {%1, %2};" : "=l"(u) : "f"(lo), "f"(hi));
    return u;
}

__device__ __forceinline__ uint32_t smem_u32(const void* p) {
    uint32_t a;
    asm("{ .reg .u64 t; cvta.to.shared.u64 t, %1; cvt.u32.u64 %0, t; }"
        : "=r"(a) : "l"(p));
    return a;
}

__device__ __forceinline__ void cpa16(uint32_t s, const void* g) {
    asm volatile("cp.async.cg.shared.global [%0], [%1], 16;" :: "r"(s), "l"(g));
}

// pair index -> (m, n), n >= m, row-major upper triangle
__host__ __device__ constexpr int PM(int p) {
    return p < 6 ? 0 : p < 11 ? 1 : p < 15 ? 2 : p < 18 ? 3 : p < 20 ? 4 : 5;
}
__host__ __device__ constexpr int PN(int p) {
    return p < 6 ? p : p < 11 ? p - 5 : p < 15 ? p - 9 : p < 18 ? p - 12
         : p < 20 ? p - 14 : 5;
}

// ---------------- scratch (device globals; no runtime allocation) ----------------
__device__ float2 d_V[BF * 216];   // V[bf][k][m][n]
__device__ float2 d_C[BF * 36];    // C[bf][m][n] = sum_t x x^H (unnormalized)
__device__ float2 d_Q[BF * 36];    // working Q
__device__ float  d_part[BF];      // per-(b,f) partial trace(Q C Q^H)
__device__ float  d_sinv[BB];      // 1/scale
__device__ float  d_rs[BB];        // rsqrt(max(scale,1e-6))

// accumulate one chunk from planar smem
template<int P0, int NP>
__device__ __forceinline__ void cov_accum(const float* __restrict__ S, int c,
                                          int len, int lane,
                                          ULL (&acc)[NP][6], ULL (&accC)[NP])
{
    const float* srb = S + c * CH_STRIDE;
    const float* sxr = srb + RG_STRIDE;
    const float* sxi = srb + 2 * RG_STRIDE;
    for (int t = lane; t < len; t += 32) {
        float xr6[6], xi6[6];
        ULL rv2[6];
        #pragma unroll
        for (int m = 0; m < 6; ++m) {
            xr6[m] = sxr[m * M_STRIDE + t];
            xi6[m] = sxi[m * M_STRIDE + t];
            float rk = srb[m * M_STRIDE + t];
            rv2[m] = pk(rk, rk);
        }
        #pragma unroll
        for (int j = 0; j < NP; ++j) {
            const int m = PM(P0 + j), n = PN(P0 + j);
            // cr = (crR, crI): crR = ax*bx + ay*by ; crI = ay*bx - ax*by
            ULL axy = pk(xr6[m],  xi6[m]);
            ULL ayx = pk(xi6[m], -xr6[m]);
            ULL bxx = pk(xr6[n],  xr6[n]);
            ULL byy = pk(xi6[n],  xi6[n]);
            ULL cr;
            MUL_F32X2(cr, ayx, byy);
            FMA_F32X2(cr, axy, bxx, cr);
            ADD_F32X2(accC[j], accC[j], cr);
            #pragma unroll
            for (int k = 0; k < 6; ++k)
                FMA_F32X2(acc[j][k], rv2[k], cr, acc[j][k]);
        }
    }
}

// per-warp main: pipelined chunk waits (CONVERGED barriers: every one of the
// 128 threads runs exactly this sequence once), then aliased partial store.
template<int P0, int NP>
__device__ __forceinline__ void cov_main(const float* __restrict__ S,
                                         int wid, int lane, float* red)
{
    ULL acc[NP][6];
    ULL accC[NP];
    #pragma unroll
    for (int j = 0; j < NP; ++j) {
        accC[j] = 0;
        #pragma unroll
        for (int k = 0; k < 6; ++k) acc[j][k] = 0;
    }

    asm volatile("cp.async.wait_group 3;" ::: "memory");
    __syncthreads();
    cov_accum<P0, NP>(S, 0, 256, lane, acc, accC);
    asm volatile("cp.async.wait_group 2;" ::: "memory");
    __syncthreads();
    cov_accum<P0, NP>(S, 1, 256, lane, acc, accC);
    asm volatile("cp.async.wait_group 1;" ::: "memory");
    __syncthreads();
    cov_accum<P0, NP>(S, 2, 256, lane, acc, accC);
    asm volatile("cp.async.wait_group 0;" ::: "memory");
    __syncthreads();
    cov_accum<P0, NP>(S, 3, 232, lane, acc, accC);

    __syncthreads();   // all chunks dead block-wide; red alias now safe

    // partials: red[(wid*32+lane)*97 + j*16 + {0..5 aR, 6..11 aI, 12 cR, 13 cI}]
    float* rp = red + (size_t)(wid * 32 + lane) * 97;
    #pragma unroll
    for (int j = 0; j < NP; ++j) {
        #pragma unroll
        for (int k = 0; k < 6; ++k) {
            float aR, aI;
            UNPACK_F32X2(aR, aI, acc[j][k]);
            rp[j * 16 + k]     = aR;
            rp[j * 16 + 6 + k] = aI;
        }
        float cR, cI;
        UNPACK_F32X2(cR, cI, accC[j]);
        rp[j * 16 + 12] = cR;
        rp[j * 16 + 13] = cI;
    }
}

// ---------------- K1: weighted covariances V, plain covariance C, Q copy ----------
__global__ __launch_bounds__(128, 2) void k_cov(
    const float* __restrict__ r,
    const float* __restrict__ Qre, const float* __restrict__ Qim,
    const float* __restrict__ xre, const float* __restrict__ xim)
{
    extern __shared__ float smem[];
    float* red  = smem;            // aliased after compute
    float* sred = smem + 12416;

    const int bf  = blockIdx.x;
    const int tid = threadIdx.x;
    const int wid = tid >> 5, lane = tid & 31;
    const size_t base = (size_t)bf * 6000;
    const uint32_t sbase = smem_u32(smem);

    if (tid < 36) {
        const size_t qi = (size_t)bf * 36 + tid;
        d_Q[qi] = make_float2(Qre[qi], Qim[qi]);
    }

    // issue all 4 chunk groups up front (16B cp.async, rows 16B-aligned)
    #pragma unroll
    for (int c = 0; c < 4; ++c) {
        const int len  = (c == 3) ? 232 : 256;
        const int len4 = len >> 2;            // float4 per (region, m) row
        const int nf4  = 18 * len4;           // 3 regions x 6 m
        for (int i = tid; i < nf4; i += 128) {
            const int row = i / len4, j = i % len4;
            const int region = row / 6, m = row % 6;
            const float* sp = (region == 0) ? r : (region == 1) ? xre : xim;
            const float* g  = sp + base + m * 1000 + 256 * c + 4 * j;
            const uint32_t s = sbase +
                4u * (c * CH_STRIDE + region * RG_STRIDE + m * M_STRIDE + 4 * j);
            cpa16(s, g);
        }
        asm volatile("cp.async.commit_group;" ::: "memory");
    }

    if      (wid == 0) cov_main<0, 6>(smem, 0, lane, red);
    else if (wid == 1) cov_main<6, 5>(smem, 1, lane, red);
    else if (wid == 2) cov_main<11,5>(smem, 2, lane, red);
    else               cov_main<16,5>(smem, 3, lane, red);
    __syncthreads();   // partials stored -> reduce

    // reduce: 294 output scalars = 21 pairs x 14 components
    for (int s = tid; s < 294; s += 128) {
        const int pair = s / 14, comp = s % 14;
        const int w  = pair < 6 ? 0 : pair < 11 ? 1 : pair < 16 ? 2 : 3;
        const int j  = pair - (w == 0 ? 0 : w == 1 ? 6 : w == 2 ? 11 : 16);
        float acc = 0.f;
        const float* rp = red + (size_t)(w * 32) * 97 + j * 16 + comp;
        #pragma unroll 8
        for (int l = 0; l < 32; ++l) acc += rp[l * 97];
        sred[s] = acc;
    }
    __syncthreads();

    if (tid < NPAIR) {
        const float* s = sred + tid * 14;
        const int m = PM(tid), n = PN(tid);
        const float invT = 1.0f / (float)TTDIM;
        float2* Vg = d_V + (size_t)bf * 216;
        #pragma unroll
        for (int k = 0; k < 6; ++k) {
            float vr = s[k] * invT + ((m == n) ? EPSV : 0.f);
            float vi = s[6 + k] * invT;
            Vg[(k * 6 + m) * 6 + n] = make_float2(vr,  vi);
            Vg[(k * 6 + n) * 6 + m] = make_float2(vr, -vi);
        }
        float2* Cg = d_C + (size_t)bf * 36;
        Cg[m * 6 + n] = make_float2(s[12],  s[13]);
        Cg[n * 6 + m] = make_float2(s[12], -s[13]);
    }
}

// ---------------- K2: one ISS iteration, single warp per (b,f) --------------------
__global__ __launch_bounds__(32) void k_iss(int apply_pre)
{
    __shared__ float2 sV[216], sC[36], sQ[36], sVq[36], sv[6], sq[6];
    const int bf = blockIdx.x, b = bf / FF;
    const int lane = threadIdx.x;

    for (int i = lane; i < 216; i += 32) sV[i] = d_V[(size_t)bf * 216 + i];
    const float rs = apply_pre ? d_rs[b] : 1.0f;
    for (int i = lane; i < 36; i += 32) {
        sC[i] = d_C[(size_t)bf * 36 + i];
        float2 q = d_Q[(size_t)bf * 36 + i];
        sQ[i] = make_float2(q.x * rs, q.y * rs);
    }
    __syncwarp();

    for (int k = 0; k < 6; ++k) {
        if (lane < 6) sq[lane] = sQ[k * 6 + lane];       // snapshot row k
        __syncwarp();
        for (int it = lane; it < 36; it += 32) {          // Vq = V * conj(q)
            const int kk = it / 6, m = it % 6;
            float ar = 0.f, ai = 0.f;
            #pragma unroll
            for (int n = 0; n < 6; ++n) {
                float2 V = sV[(kk * 6 + m) * 6 + n];
                float2 q = sq[n];
                ar += V.x * q.x + V.y * q.y;
                ai += V.y * q.x - V.x * q.y;
            }
            sVq[it] = make_float2(ar, ai);
        }
        __syncwarp();
        if (lane < 6) {
            const int kk = lane;
            float qvq = 0.f, nr = 0.f, ni = 0.f;
            #pragma unroll
            for (int m = 0; m < 6; ++m) {
                float2 q = sq[m], Vq = sVq[kk * 6 + m], Qe = sQ[kk * 6 + m];
                qvq += q.x * Vq.x - q.y * Vq.y;
                nr  += Qe.x * Vq.x - Qe.y * Vq.y;
                ni  += Qe.x * Vq.y + Qe.y * Vq.x;
            }
            qvq = fmaxf(qvq, EPS2V);
            const float inv = 1.0f / qvq;
            float2 vv = make_float2(nr * inv, ni * inv);
            if (kk == k) vv = make_float2(1.0f - rsqrtf(qvq), 0.f);
            sv[kk] = vv;
        }
        __syncwarp();
        for (int it = lane; it < 36; it += 32) {          // Q -= v outer q
            const int kk = it / 6, m = it % 6;
            float2 vv = sv[kk], q = sq[m], Qe = sQ[it];
            Qe.x -= vv.x * q.x - vv.y * q.y;
            Qe.y -= vv.x * q.y + vv.y * q.x;
            sQ[it] = Qe;
        }
        __syncwarp();
    }

    // trace(Q C Q^H)
    for (int it = lane; it < 36; it += 32) {
        const int m = it / 6, n = it % 6;
        float ar = 0.f, ai = 0.f;
        #pragma unroll
        for (int p = 0; p < 6; ++p) {
            float2 a = sQ[m * 6 + p], c = sC[p * 6 + n];
            ar += a.x * c.x - a.y * c.y;
            ai += a.x * c.y + a.y * c.x;
        }
        sVq[it] = make_float2(ar, ai);
    }
    __syncwarp();
    float s = 0.f;
    for (int it = lane; it < 36; it += 32) {
        float2 qc = sVq[it], q = sQ[it];
        s += qc.x * q.x + qc.y * q.y;
    }
    #pragma unroll
    for (int o = 16; o; o >>= 1) s += __shfl_down_sync(0xffffffffu, s, o);
    if (lane == 0) d_part[bf] = s;
    for (int i = lane; i < 36; i += 32) d_Q[(size_t)bf * 36 + i] = sQ[i];
}

// ---------------- K3: per-batch scale from trace partials -------------------------
__global__ __launch_bounds__(256) void k_scale()
{
    __shared__ float red[256];
    const int b = blockIdx.x, tid = threadIdx.x;
    float s = 0.f;
    for (int i = tid; i < FF; i += 256) s += d_part[b * FF + i];
    red[tid] = s;
    __syncthreads();
    for (int o = 128; o > 0; o >>= 1) {
        if (tid < o) red[tid] += red[tid + o];
        __syncthreads();
    }
    if (tid == 0) {
        const float scale = red[0] / (float)(FF * 6 * TTDIM);
        d_sinv[b] = 1.0f / scale;
        d_rs[b]   = rsqrtf(fmaxf(scale, 1e-6f));
    }
}

// ---------------- K4: final Q output + xt = |Q2 x|^2 / scale2 ---------------------
__global__ __launch_bounds__(256) void k_final(
    const float* __restrict__ xre, const float* __restrict__ xim,
    float* __restrict__ out)
{
    __shared__ float sQr[36], sQi[36];
    __shared__ float sI;
    const int bf = blockIdx.x, b = bf / FF, tid = threadIdx.x;
    if (tid < 36) {
        float2 q = d_Q[(size_t)bf * 36 + tid];
        sQr[tid] = q.x;
        sQi[tid] = q.y;
        out[(size_t)bf * 36 + tid] = q.x * d_rs[b];
    }
    if (tid == 64) sI = d_sinv[b];
    __syncthreads();

    if (tid < 250) {
        const size_t base = (size_t)bf * 6000;
        const float4* xr4 = reinterpret_cast<const float4*>(xre + base);
        const float4* xi4 = reinterpret_cast<const float4*>(xim + base);
        float4* xt4 = reinterpret_cast<float4*>(out + (size_t)NQ + base);
        const float inv = sI;

        float4 vr[6], vi[6];
        #pragma unroll
        for (int n = 0; n < 6; ++n) {
            vr[n] = xr4[n * 250 + tid];
            vi[n] = xi4[n * 250 + tid];
        }
        #pragma unroll
        for (int m = 0; m < 6; ++m) {
            float4 ar = make_float4(0,0,0,0), ai = make_float4(0,0,0,0);
            #pragma unroll
            for (int n = 0; n < 6; ++n) {
                const float qr = sQr[m * 6 + n], qi = sQi[m * 6 + n];
                ar.x = fmaf(qr, vr[n].x, fmaf(-qi, vi[n].x, ar.x));
                ar.y = fmaf(qr, vr[n].y, fmaf(-qi, vi[n].y, ar.y));
                ar.z = fmaf(qr, vr[n].z, fmaf(-qi, vi[n].z, ar.z));
                ar.w = fmaf(qr, vr[n].w, fmaf(-qi, vi[n].w, ar.w));
                ai.x = fmaf(qr, vi[n].x, fmaf(qi, vr[n].x, ai.x));
                ai.y = fmaf(qr, vi[n].y, fmaf(qi, vr[n].y, ai.y));
                ai.z = fmaf(qr, vi[n].z, fmaf(qi, vr[n].z, ai.z));
                ai.w = fmaf(qr, vi[n].w, fmaf(qi, vr[n].w, ai.w));
            }
            float4 o4;
            o4.x = (ar.x * ar.x + ai.x * ai.x) * inv;
            o4.y = (ar.y * ar.y + ai.y * ai.y) * inv;
            o4.z = (ar.z * ar.z + ai.z * ai.z) * inv;
            o4.w = (ar.w * ar.w + ai.w * ai.w) * inv;
            xt4[m * 250 + tid] = o4;
        }
    }
}

// ---------------- launch ----------------
extern "C" void kernel_launch(void* const* d_in, const int* in_sizes, int n_in,
                              void* d_out, int out_size)
{
    const float* r   = (const float*)d_in[0];
    const float* Qre = (const float*)d_in[1];
    const float* Qim = (const float*)d_in[2];
    const float* xre = (const float*)d_in[3];
    const float* xim = (const float*)d_in[4];
    float* out = (float*)d_out;

    const int smem_cov = SMEM_FLOATS * (int)sizeof(float);   // 73728 B
    cudaFuncSetAttribute(k_cov, cudaFuncAttributeMaxDynamicSharedMemorySize, smem_cov);

    k_cov<<<BF, 128, smem_cov>>>(r, Qre, Qim, xre, xim);
    k_iss<<<BF, 32>>>(0);
    k_scale<<<BB, 256>>>();
    k_iss<<<BF, 32>>>(1);
    k_scale<<<BB, 256>>>();
    k_final<<<BF, 256>>>(xre, xim, out);
}